// round 11
// baseline (speedup 1.0000x reference)
#include <cuda_runtime.h>
#include <cstdint>

#define Bq    4
#define Nq    2048
#define DINq  256
#define DOUTq 256
#define Hq    4
#define HDq   64
#define NEG_SLOPE 0.2f

#define NC    (Nq / 32)          // 64 j-chunks
#define SH_STRIDE 264            // h stage row stride (words), bank-conflict-free
#define SH_WORDS  (2 * 32 * SH_STRIDE)        // 16896
#define SP_WORDS  (2 * Hq * 32 * 36)          // 9216
#define SMEM_BYTES ((SH_WORDS + SP_WORDS) * 4)  // 104448

// ---------------- scratch (no allocation allowed) ----------------
__device__ float g_h[Bq * Nq * DOUTq];       // 8 MB: h = x @ W^T
__device__ float g_ssrc[Bq * Nq * Hq];
__device__ float g_sdst[Bq * Nq * Hq];

// ---------------- packed f32x2 helpers (gemm) ----------------
__device__ __forceinline__ void ffma2(unsigned long long& acc,
                                      unsigned long long p,
                                      unsigned long long h) {
    asm("fma.rn.f32x2 %0, %1, %2, %0;" : "+l"(acc) : "l"(p), "l"(h));
}
__device__ __forceinline__ unsigned long long pack2(float lo, float hi) {
    unsigned long long r;
    asm("mov.b64 %0, {%1, %2};" : "=l"(r) : "f"(lo), "f"(hi));
    return r;
}
__device__ __forceinline__ void unpack2(unsigned long long v, float& lo, float& hi) {
    asm("mov.b64 {%0, %1}, %2;" : "=f"(lo), "=f"(hi) : "l"(v));
}

// ---------------- tf32 mma helpers ----------------
__device__ __forceinline__ uint32_t f2tf32(float f) {
    uint32_t r;
    asm("cvt.rna.tf32.f32 %0, %1;" : "=r"(r) : "f"(f));
    return r;
}
__device__ __forceinline__ void mma_tf32(float* d, const uint32_t* a, const uint32_t* b) {
    asm volatile(
        "mma.sync.aligned.m16n8k8.row.col.f32.tf32.tf32.f32 "
        "{%0,%1,%2,%3}, {%4,%5,%6,%7}, {%8,%9}, {%0,%1,%2,%3};"
        : "+f"(d[0]), "+f"(d[1]), "+f"(d[2]), "+f"(d[3])
        : "r"(a[0]), "r"(a[1]), "r"(a[2]), "r"(a[3]), "r"(b[0]), "r"(b[1]));
}

// ---------------- cp.async helpers ----------------
__device__ __forceinline__ void cp_async16(uint32_t dst_smem, const float* src) {
    asm volatile("cp.async.cg.shared.global [%0], [%1], 16;" :: "r"(dst_smem), "l"(src));
}
#define CP_COMMIT() asm volatile("cp.async.commit_group;")
#define CP_WAIT0()  asm volatile("cp.async.wait_group 0;" ::: "memory")

// =====================================================================
// Kernel 1: h = x @ W^T.  128x64 tile, 256 threads, 8x4 micro-tile.
// =====================================================================
__global__ __launch_bounds__(256) void gemm_xWT_kernel(const float* __restrict__ x,
                                                       const float* __restrict__ W) {
    __shared__ float as[16][132];
    __shared__ float bs[16][68];

    const int tid = threadIdx.x;
    const int tx = tid & 15;
    const int ty = tid >> 4;
    const int row0 = blockIdx.x * 128;
    const int col0 = blockIdx.y * 64;

    unsigned long long acc2[4][4];
#pragma unroll
    for (int i = 0; i < 4; i++)
#pragma unroll
        for (int j = 0; j < 4; j++) acc2[i][j] = 0ull;

    const int arow = tid >> 1;
    const int aq   = (tid & 1) * 8;
    const int brow = tid >> 2;
    const int bq   = (tid & 3) * 4;
    const float* xp = x + (size_t)(row0 + arow) * DINq + aq;
    const float* wp = W + (size_t)(col0 + brow) * DINq + bq;

    for (int kc = 0; kc < DINq; kc += 16) {
        float4 v0 = *(const float4*)(xp + kc);
        float4 v1 = *(const float4*)(xp + kc + 4);
        float4 wv = *(const float4*)(wp + kc);
        as[aq + 0][arow] = v0.x; as[aq + 1][arow] = v0.y;
        as[aq + 2][arow] = v0.z; as[aq + 3][arow] = v0.w;
        as[aq + 4][arow] = v1.x; as[aq + 5][arow] = v1.y;
        as[aq + 6][arow] = v1.z; as[aq + 7][arow] = v1.w;
        bs[bq + 0][brow] = wv.x; bs[bq + 1][brow] = wv.y;
        bs[bq + 2][brow] = wv.z; bs[bq + 3][brow] = wv.w;
        __syncthreads();

#pragma unroll
        for (int k = 0; k < 16; k++) {
            float a8[8], b4[4];
            *(float4*)a8       = *(const float4*)&as[k][ty * 8];
            *(float4*)(a8 + 4) = *(const float4*)&as[k][ty * 8 + 4];
            *(float4*)b4       = *(const float4*)&bs[k][tx * 4];
            unsigned long long bp[4];
#pragma unroll
            for (int j = 0; j < 4; j++) bp[j] = pack2(b4[j], b4[j]);
#pragma unroll
            for (int i = 0; i < 4; i++) {
                unsigned long long ap = pack2(a8[2 * i], a8[2 * i + 1]);
#pragma unroll
                for (int j = 0; j < 4; j++) ffma2(acc2[i][j], ap, bp[j]);
            }
        }
        __syncthreads();
    }

#pragma unroll
    for (int i = 0; i < 4; i++) {
        float lo[4], hi[4];
#pragma unroll
        for (int j = 0; j < 4; j++) unpack2(acc2[i][j], lo[j], hi[j]);
        float4 o0; o0.x = lo[0]; o0.y = lo[1]; o0.z = lo[2]; o0.w = lo[3];
        float4 o1; o1.x = hi[0]; o1.y = hi[1]; o1.z = hi[2]; o1.w = hi[3];
        const int r = row0 + ty * 8 + 2 * i;
        *(float4*)&g_h[(size_t)(r + 0) * DOUTq + col0 + tx * 4] = o0;
        *(float4*)&g_h[(size_t)(r + 1) * DOUTq + col0 + tx * 4] = o1;
    }
}

// =====================================================================
// Kernel 2: per-(row,head) scores via warp dot products
// =====================================================================
__global__ __launch_bounds__(256) void score_kernel(const float* __restrict__ a_src,
                                                    const float* __restrict__ a_dst) {
    const int task = blockIdx.x * 8 + (threadIdx.x >> 5);   // row*4 + head
    const int ln = threadIdx.x & 31;
    const int row = task >> 2;
    const int head = task & 3;

    const float* hp = g_h + (size_t)row * DOUTq + head * HDq;
    float v0 = hp[ln], v1 = hp[ln + 32];
    float s1 = v0 * a_src[head * HDq + ln] + v1 * a_src[head * HDq + ln + 32];
    float s2 = v0 * a_dst[head * HDq + ln] + v1 * a_dst[head * HDq + ln + 32];
#pragma unroll
    for (int off = 16; off > 0; off >>= 1) {
        s1 += __shfl_xor_sync(0xFFFFFFFFu, s1, off);
        s2 += __shfl_xor_sync(0xFFFFFFFFu, s2, off);
    }
    if (ln == 0) {
        g_ssrc[task] = s1;
        g_sdst[task] = s2;
    }
}

// =====================================================================
// Kernel 3: tensor-core aggregation (tf32 mma) + fused softmax denom.
// Block = 256 thr / 8 warps, i-tile = 32, grid (N/32, B).
// Warp w = (head = w&3, nhalf = w>>2): m=32, n=32.
// Per chunk: the 32x256 h tile is staged into double-buffered smem via
// coalesced cp.async (issued right after the barrier, waited next iter).
// B fragments come from smem with conflict-free LDS.32 (stride 264).
// One barrier per chunk; sP and sH both double-buffered.
// =====================================================================
__global__ __launch_bounds__(256, 2) void agg_mma_kernel(const float* __restrict__ adj,
                                                         float* __restrict__ out) {
    extern __shared__ float smem[];
    float* sH = smem;                                  // [2][32][264]
    uint32_t* sP = (uint32_t*)(smem + SH_WORDS);       // [2][4][32][36]

    const int t = threadIdx.x;
    const int w = t >> 5;
    const int lane = t & 31;
    const int head = w & 3;
    const int nh = w >> 2;
    const int g = lane >> 2;
    const int ct = lane & 3;
    const int b = blockIdx.y;
    const int i0 = blockIdx.x * 32;
    const int bN = b * Nq;
    const int colbase = head * HDq + nh * 32;

    // staging geometry: 8 threads per row, 16B units
    const int srow = t >> 3;
    const int sseg = (t & 7) * 4;                      // float offset
    const uint32_t sh_u32 = (uint32_t)__cvta_generic_to_shared(sH);
    const float* hstage_src = g_h + (size_t)bN * DOUTq + (size_t)srow * DOUTq + sseg;

    // hoisted ssrc for this warp's 4 P-rows
    float4 ssr[4];
#pragma unroll
    for (int r = 0; r < 4; r++)
        ssr[r] = *(const float4*)&g_ssrc[(size_t)(bN + i0 + w * 4 + r) * 4];

    float d[2][4][4];
    float dones[2][4];
#pragma unroll
    for (int s = 0; s < 2; s++) {
#pragma unroll
        for (int nt = 0; nt < 4; nt++)
#pragma unroll
            for (int q = 0; q < 4; q++) d[s][nt][q] = 0.f;
#pragma unroll
        for (int q = 0; q < 4; q++) dones[s][q] = 0.f;
    }

    uint32_t bones[2];
    bones[0] = bones[1] = (g == 0) ? __float_as_uint(1.0f) : 0u;

    const float* adjbase = adj + (size_t)(bN + i0 + w * 4) * Nq;

    // prologue: chunk 0 adj/sdst regs + stage chunk 0
    float av[4];
    float4 sd4;
    sd4 = __ldg((const float4*)&g_sdst[(size_t)(bN + lane) * 4]);
#pragma unroll
    for (int r = 0; r < 4; r++)
        av[r] = __ldg(adjbase + (size_t)r * Nq + lane);

    {
        uint32_t dst = sh_u32 + (uint32_t)(srow * SH_STRIDE + sseg) * 4;
#pragma unroll
        for (int q = 0; q < 8; q++)
            cp_async16(dst + q * 32 * 4, hstage_src + q * 32);
        CP_COMMIT();
    }

    for (int c = 0; c < NC; c++) {
        const int j0 = c * 32;
        const int buf = c & 1;

        // ---------- P-phase: rows w*4..w*4+3, all 4 heads ----------
        uint32_t* sPb = sP + buf * (Hq * 32 * 36);
#pragma unroll
        for (int r = 0; r < 4; r++) {
            const int row = w * 4 + r;
            float avr = av[r];
            float4 ss = ssr[r];
            float e0 = ss.x + sd4.x; e0 = fmaxf(e0, NEG_SLOPE * e0);
            float e1 = ss.y + sd4.y; e1 = fmaxf(e1, NEG_SLOPE * e1);
            float e2 = ss.z + sd4.z; e2 = fmaxf(e2, NEG_SLOPE * e2);
            float e3 = ss.w + sd4.w; e3 = fmaxf(e3, NEG_SLOPE * e3);
            sPb[0 * 1152 + row * 36 + lane] = f2tf32(avr * __expf(e0));
            sPb[1 * 1152 + row * 36 + lane] = f2tf32(avr * __expf(e1));
            sPb[2 * 1152 + row * 36 + lane] = f2tf32(avr * __expf(e2));
            sPb[3 * 1152 + row * 36 + lane] = f2tf32(avr * __expf(e3));
        }

        // ---------- prefetch next chunk's adj/sdst ----------
        if (c + 1 < NC) {
            const int j1 = j0 + 32;
            sd4 = __ldg((const float4*)&g_sdst[(size_t)(bN + j1 + lane) * 4]);
#pragma unroll
            for (int r = 0; r < 4; r++)
                av[r] = __ldg(adjbase + (size_t)r * Nq + j1 + lane);
        }

        // ---------- wait for this chunk's h stage, then barrier ----------
        CP_WAIT0();
        __syncthreads();

        // ---------- stage NEXT chunk's h tile (async, rides under mma) ----
        if (c + 1 < NC) {
            const int nbuf = (c + 1) & 1;
            uint32_t dst = sh_u32 + (uint32_t)(nbuf * (32 * SH_STRIDE) + srow * SH_STRIDE + sseg) * 4;
            const float* src = hstage_src + (size_t)(j0 + 32) * DOUTq;
#pragma unroll
            for (int q = 0; q < 8; q++)
                cp_async16(dst + q * 32 * 4, src + q * 32);
            CP_COMMIT();
        }

        // ---------- mma-phase: head, n-half ----------
        const float* sHb = sH + buf * (32 * SH_STRIDE) + colbase + g;
        const uint32_t* sPh = sP + buf * (Hq * 32 * 36) + head * 1152;
#pragma unroll
        for (int kk = 0; kk < 4; kk++) {
            const int r0 = kk * 8 + ct;
            uint32_t bf[4][2];
#pragma unroll
            for (int nt = 0; nt < 4; nt++) {
                bf[nt][0] = f2tf32(sHb[r0 * SH_STRIDE + nt * 8]);
                bf[nt][1] = f2tf32(sHb[(r0 + 4) * SH_STRIDE + nt * 8]);
            }
            const int acl = kk * 8 + ct;
#pragma unroll
            for (int s = 0; s < 2; s++) {
                const int ar = s * 16 + g;
                uint32_t af[4];
                af[0] = sPh[ar * 36 + acl];
                af[1] = sPh[(ar + 8) * 36 + acl];
                af[2] = sPh[ar * 36 + acl + 4];
                af[3] = sPh[(ar + 8) * 36 + acl + 4];
#pragma unroll
                for (int nt = 0; nt < 4; nt++) mma_tf32(d[s][nt], af, bf[nt]);
                mma_tf32(dones[s], af, bones);
            }
        }
    }

    // ---------- epilogue: normalize and store ----------
#pragma unroll
    for (int s = 0; s < 2; s++) {
        float lA = __shfl_sync(0xFFFFFFFFu, dones[s][0], lane & ~3);
        float lB = __shfl_sync(0xFFFFFFFFu, dones[s][2], lane & ~3);
        float liA = 1.0f / lA;
        float liB = 1.0f / lB;
        const int rowA = i0 + s * 16 + g;
        const int rowB = rowA + 8;
        const int col = colbase + 2 * ct;
#pragma unroll
        for (int nt = 0; nt < 4; nt++) {
            float2 oA; oA.x = d[s][nt][0] * liA; oA.y = d[s][nt][1] * liA;
            float2 oB; oB.x = d[s][nt][2] * liB; oB.y = d[s][nt][3] * liB;
            *(float2*)&out[(size_t)(bN + rowA) * DOUTq + col + nt * 8] = oA;
            *(float2*)&out[(size_t)(bN + rowB) * DOUTq + col + nt * 8] = oB;
        }
    }
}

// =====================================================================
extern "C" void kernel_launch(void* const* d_in, const int* in_sizes, int n_in,
                              void* d_out, int out_size) {
    const float* x     = (const float*)d_in[0];   // [B,N,DIN]
    const float* adj   = (const float*)d_in[1];   // [B,N,N]
    const float* W     = (const float*)d_in[2];   // [DOUT,DIN]
    const float* a_src = (const float*)d_in[3];   // [H,HD]
    const float* a_dst = (const float*)d_in[4];   // [H,HD]
    float* out = (float*)d_out;                   // [B,N,DOUT]

    cudaFuncSetAttribute(agg_mma_kernel,
                         cudaFuncAttributeMaxDynamicSharedMemorySize, SMEM_BYTES);

    gemm_xWT_kernel<<<dim3((Bq * Nq) / 128, DOUTq / 64), 256>>>(x, W);
    score_kernel<<<(Bq * Nq * Hq) / 8, 256>>>(a_src, a_dst);
    agg_mma_kernel<<<dim3(Nq / 32, Bq), 256, SMEM_BYTES>>>(adj, out);
}